// round 7
// baseline (speedup 1.0000x reference)
#include <cuda_runtime.h>

// YoloLoss: N=4096, S=14, B=2, NUM_CLS=20 — single launch, spinner finalize.
// inputs: pred_tensor (N,S,S,30) f32, target_boxes (N,S,S,4) f32,
//         target_cls (N,S,S,20) f32, has_object_map (N,S,S) int32
// output: 5 f32 = (total, reg, contain_conf, no_obj, cls)

static constexpr int NSAMP = 4096;
static constexpr int S2    = 14 * 14;
static constexpr int NCELL = NSAMP * S2;   // 802816
static constexpr int CPB   = 128;          // cells (== threads) per block
static constexpr int NBLK  = NCELL / CPB;  // 6272 worker blocks (+1 spinner)

// accumulators: reg_sum(raw), contain_sum, noobj_sum(raw), cls_sum.
// zero-initialized at load; spinner resets after each run -> replay-safe.
__device__ float    g_acc[4];
__device__ unsigned g_count;

__global__ __launch_bounds__(CPB, 12) void yolo_k(
    const float* __restrict__ pred,
    const float* __restrict__ tbox,
    const float* __restrict__ tcls,
    const int* __restrict__ mask,
    float* __restrict__ out)
{
    // ---------- spinner block: finalize without a second launch ----------
    if (blockIdx.x == NBLK) {
        if (threadIdx.x == 0) {
            unsigned c;
            do {
                __nanosleep(128);
                asm volatile("ld.acquire.gpu.global.u32 %0, [%1];"
                             : "=r"(c) : "l"(&g_count));
            } while (c < (unsigned)NBLK);
            // acquire above orders these reads after all workers' releases
            float a0, a1, a2, a3;
            asm volatile("ld.acquire.gpu.global.f32 %0, [%1];" : "=f"(a0) : "l"(&g_acc[0]));
            asm volatile("ld.acquire.gpu.global.f32 %0, [%1];" : "=f"(a1) : "l"(&g_acc[1]));
            asm volatile("ld.acquire.gpu.global.f32 %0, [%1];" : "=f"(a2) : "l"(&g_acc[2]));
            asm volatile("ld.acquire.gpu.global.f32 %0, [%1];" : "=f"(a3) : "l"(&g_acc[3]));

            const float invN = 1.0f / (float)NSAMP;
            float reg_t     = 5.0f * a0 * invN;
            float contain_t = a1 * invN;
            float noobj_t   = 0.5f * a2 * invN;
            float cls_t     = a3 * invN;
            out[0] = reg_t + contain_t + noobj_t + cls_t;
            out[1] = reg_t;
            out[2] = contain_t;
            out[3] = noobj_t;
            out[4] = cls_t;

            // reset for next graph replay; kernel-end flush publishes these
            asm volatile("st.relaxed.gpu.global.f32 [%0], %1;" :: "l"(&g_acc[0]), "f"(0.0f));
            asm volatile("st.relaxed.gpu.global.f32 [%0], %1;" :: "l"(&g_acc[1]), "f"(0.0f));
            asm volatile("st.relaxed.gpu.global.f32 [%0], %1;" :: "l"(&g_acc[2]), "f"(0.0f));
            asm volatile("st.relaxed.gpu.global.f32 [%0], %1;" :: "l"(&g_acc[3]), "f"(0.0f));
            asm volatile("st.relaxed.gpu.global.u32 [%0], %1;" :: "l"(&g_count), "r"(0u));
        }
        return;
    }

    // ---------------------------- workers --------------------------------
    // pred staged at stride 31 (odd) -> conflict-free per-cell reads
    __shared__ float sp[CPB * 31];      // 15872 B
    __shared__ float smask[CPB];
    __shared__ float red[CPB / 32][4];

    const int tid = threadIdx.x;
    const long base = (long)blockIdx.x * CPB;

    // --- stage pred via float2 (30 even -> a pair never splits a cell) ---
    const float2* __restrict__ pg2 =
        reinterpret_cast<const float2*>(pred + base * 30);
#pragma unroll
    for (int i = 0; i < 15; i++) {
        int idx2 = tid + i * CPB;       // 0..1919
        float2 v = pg2[idx2];
        int e    = idx2 * 2;
        int cell = e / 30;
        int ch   = e - cell * 30;
        sp[cell * 31 + ch]     = v.x;
        sp[cell * 31 + ch + 1] = v.y;
    }
    smask[tid] = (mask[base + tid] != 0) ? 1.0f : 0.0f;
    __syncthreads();

    // --- cls loss fused into float4-streamed tcls (20%4==0: no cell split) ---
    const float4* __restrict__ cg4 =
        reinterpret_cast<const float4*>(tcls + base * 20);
    float cls = 0.0f;
#pragma unroll
    for (int i = 0; i < 5; i++) {
        int idx4 = tid + i * CPB;       // 0..639
        float4 v = cg4[idx4];
        int e    = idx4 * 4;
        int cell = e / 20;
        int ch   = e - cell * 20;       // in {0,4,8,12,16}
        const float* p = &sp[cell * 31 + 10 + ch];
        float d0 = p[0] - v.x, d1 = p[1] - v.y;
        float d2 = p[2] - v.z, d3 = p[3] - v.w;
        cls += (d0 * d0 + d1 * d1 + d2 * d2 + d3 * d3) * smask[cell];
    }

    // --- per-cell box terms ---
    const float4 tb = reinterpret_cast<const float4*>(tbox)[base + tid];
    const float  m  = smask[tid];
    const float* P  = &sp[tid * 31];

    float c0 = P[4], c1 = P[9];
    float noobj = (c0 * c0 + c1 * c1) * (1.0f - m);   // 0.5 at finalize

    const float invS = 1.0f / 14.0f;
    float gx1 = tb.x * invS - 0.5f * tb.z, gx2 = tb.x * invS + 0.5f * tb.z;
    float gy1 = tb.y * invS - 0.5f * tb.w, gy2 = tb.y * invS + 0.5f * tb.w;
    float area_g = (gx2 - gx1) * (gy2 - gy1);

    float iou0, iou1;
#pragma unroll
    for (int b = 0; b < 2; b++) {
        float px = P[5 * b + 0], py = P[5 * b + 1];
        float pw = P[5 * b + 2], ph = P[5 * b + 3];
        float px1 = px * invS - 0.5f * pw, px2 = px * invS + 0.5f * pw;
        float py1 = py * invS - 0.5f * ph, py2 = py * invS + 0.5f * ph;
        float iw = fmaxf(fminf(px2, gx2) - fmaxf(px1, gx1), 0.0f);
        float ih = fmaxf(fminf(py2, gy2) - fmaxf(py1, gy1), 0.0f);
        float inter  = iw * ih;
        float area_p = (px2 - px1) * (py2 - py1);
        float v = inter / (area_p + area_g - inter);
        if (b == 0) iou0 = v; else iou1 = v;
    }
    // jnp.argmax keeps first max on ties -> strict '>' for box 1
    const int best = (iou1 > iou0) ? 1 : 0;
    const float bx = P[5 * best + 0], by = P[5 * best + 1];
    const float bw = P[5 * best + 2], bh = P[5 * best + 3];
    const float bc = P[5 * best + 4];

    float dx = bx - tb.x, dy = by - tb.y;
    float dw = sqrtf(bw) - sqrtf(tb.z);
    float dh = sqrtf(bh) - sqrtf(tb.w);
    float regp = (dx * dx + dy * dy + dw * dw + dh * dh) * m; // L_COORD at finalize
    float dc = bc - 1.0f;
    float contain = dc * dc * m;

    // --- reduction: warp shuffle -> smem -> thread 0 fire-and-forget ---
    float v0 = regp, v1 = contain, v2 = noobj, v3 = cls;
#pragma unroll
    for (int off = 16; off > 0; off >>= 1) {
        v0 += __shfl_xor_sync(0xffffffffu, v0, off);
        v1 += __shfl_xor_sync(0xffffffffu, v1, off);
        v2 += __shfl_xor_sync(0xffffffffu, v2, off);
        v3 += __shfl_xor_sync(0xffffffffu, v3, off);
    }
    const int warp = tid >> 5;
    if ((tid & 31) == 0) {
        red[warp][0] = v0; red[warp][1] = v1;
        red[warp][2] = v2; red[warp][3] = v3;
    }
    __syncthreads();
    if (tid == 0) {
        float s0 = red[0][0] + red[1][0] + red[2][0] + red[3][0];
        float s1 = red[0][1] + red[1][1] + red[2][1] + red[3][1];
        float s2 = red[0][2] + red[1][2] + red[2][2] + red[3][2];
        float s3 = red[0][3] + red[1][3] + red[2][3] + red[3][3];
        atomicAdd(&g_acc[0], s0);   // return unused -> RED, fire-and-forget
        atomicAdd(&g_acc[1], s1);
        atomicAdd(&g_acc[2], s2);
        atomicAdd(&g_acc[3], s3);
        // release-ordered fire-and-forget counter bump: orders this thread's
        // REDs above without consuming a return value (no round trip).
        asm volatile("red.release.gpu.global.add.u32 [%0], %1;"
                     :: "l"(&g_count), "r"(1u) : "memory");
    }
}

extern "C" void kernel_launch(void* const* d_in, const int* in_sizes, int n_in,
                              void* d_out, int out_size)
{
    const float* pred = (const float*)d_in[0];
    const float* tbox = (const float*)d_in[1];
    const float* tcls = (const float*)d_in[2];
    const int*   mask = (const int*)d_in[3];
    float* out = (float*)d_out;

    yolo_k<<<NBLK + 1, CPB>>>(pred, tbox, tcls, mask, out);
}

// round 8
// speedup vs baseline: 1.4020x; 1.4020x over previous
#include <cuda_runtime.h>

// YoloLoss: N=4096, S=14, B=2, NUM_CLS=20 — main (fire-and-forget REDs) +
// tiny finalize kernel. No gpu-scope fences anywhere (they L1-flush per
// block and cost ~15us at this grid size — measured R3/R5/R7).
// inputs: pred_tensor (N,S,S,30) f32, target_boxes (N,S,S,4) f32,
//         target_cls (N,S,S,20) f32, has_object_map (N,S,S) int32
// output: 5 f32 = (total, reg, contain_conf, no_obj, cls)

static constexpr int NSAMP = 4096;
static constexpr int S2    = 14 * 14;
static constexpr int NCELL = NSAMP * S2;   // 802816
static constexpr int CPB   = 128;          // cells (== threads) per block
static constexpr int NBLK  = NCELL / CPB;  // 6272

// accumulators: reg_sum(raw), contain_sum, noobj_sum(raw), cls_sum.
// zero-initialized at load; finalize_k resets them each run (kernel-boundary
// ordering) -> every graph replay starts clean.
__device__ float g_acc[4];

__global__ __launch_bounds__(CPB, 12) void yolo_k(
    const float* __restrict__ pred,
    const float* __restrict__ tbox,
    const float* __restrict__ tcls,
    const int* __restrict__ mask)
{
    // pred staged at stride 31 (odd) -> conflict-free per-cell reads
    __shared__ float sp[CPB * 31];      // 15872 B
    __shared__ float smask[CPB];
    __shared__ float red[CPB / 32][4];

    const int tid = threadIdx.x;
    const long base = (long)blockIdx.x * CPB;

    // --- stage pred via float2 (30 even -> a pair never splits a cell) ---
    const float2* __restrict__ pg2 =
        reinterpret_cast<const float2*>(pred + base * 30);
#pragma unroll
    for (int i = 0; i < 15; i++) {
        int idx2 = tid + i * CPB;       // 0..1919
        float2 v = pg2[idx2];
        int e    = idx2 * 2;
        int cell = e / 30;
        int ch   = e - cell * 30;
        sp[cell * 31 + ch]     = v.x;
        sp[cell * 31 + ch + 1] = v.y;
    }
    smask[tid] = (mask[base + tid] != 0) ? 1.0f : 0.0f;
    __syncthreads();

    // --- cls loss fused into float4-streamed tcls (20%4==0: no cell split) ---
    const float4* __restrict__ cg4 =
        reinterpret_cast<const float4*>(tcls + base * 20);
    float cls = 0.0f;
#pragma unroll
    for (int i = 0; i < 5; i++) {
        int idx4 = tid + i * CPB;       // 0..639
        float4 v = cg4[idx4];
        int e    = idx4 * 4;
        int cell = e / 20;
        int ch   = e - cell * 20;       // in {0,4,8,12,16}
        const float* p = &sp[cell * 31 + 10 + ch];
        float d0 = p[0] - v.x, d1 = p[1] - v.y;
        float d2 = p[2] - v.z, d3 = p[3] - v.w;
        cls += (d0 * d0 + d1 * d1 + d2 * d2 + d3 * d3) * smask[cell];
    }

    // --- per-cell box terms ---
    const float4 tb = reinterpret_cast<const float4*>(tbox)[base + tid];
    const float  m  = smask[tid];
    const float* P  = &sp[tid * 31];

    float c0 = P[4], c1 = P[9];
    float noobj = (c0 * c0 + c1 * c1) * (1.0f - m);   // 0.5 at finalize

    const float invS = 1.0f / 14.0f;
    float gx1 = tb.x * invS - 0.5f * tb.z, gx2 = tb.x * invS + 0.5f * tb.z;
    float gy1 = tb.y * invS - 0.5f * tb.w, gy2 = tb.y * invS + 0.5f * tb.w;
    float area_g = (gx2 - gx1) * (gy2 - gy1);

    float iou0, iou1;
#pragma unroll
    for (int b = 0; b < 2; b++) {
        float px = P[5 * b + 0], py = P[5 * b + 1];
        float pw = P[5 * b + 2], ph = P[5 * b + 3];
        float px1 = px * invS - 0.5f * pw, px2 = px * invS + 0.5f * pw;
        float py1 = py * invS - 0.5f * ph, py2 = py * invS + 0.5f * ph;
        float iw = fmaxf(fminf(px2, gx2) - fmaxf(px1, gx1), 0.0f);
        float ih = fmaxf(fminf(py2, gy2) - fmaxf(py1, gy1), 0.0f);
        float inter  = iw * ih;
        float area_p = (px2 - px1) * (py2 - py1);
        float v = inter / (area_p + area_g - inter);
        if (b == 0) iou0 = v; else iou1 = v;
    }
    // jnp.argmax keeps first max on ties -> strict '>' for box 1
    const int best = (iou1 > iou0) ? 1 : 0;
    const float bx = P[5 * best + 0], by = P[5 * best + 1];
    const float bw = P[5 * best + 2], bh = P[5 * best + 3];
    const float bc = P[5 * best + 4];

    float dx = bx - tb.x, dy = by - tb.y;
    float dw = sqrtf(bw) - sqrtf(tb.z);
    float dh = sqrtf(bh) - sqrtf(tb.w);
    float regp = (dx * dx + dy * dy + dw * dw + dh * dh) * m; // L_COORD at finalize
    float dc = bc - 1.0f;
    float contain = dc * dc * m;

    // --- reduction: warp shuffle -> smem -> 4 fire-and-forget REDs ---
    float v0 = regp, v1 = contain, v2 = noobj, v3 = cls;
#pragma unroll
    for (int off = 16; off > 0; off >>= 1) {
        v0 += __shfl_xor_sync(0xffffffffu, v0, off);
        v1 += __shfl_xor_sync(0xffffffffu, v1, off);
        v2 += __shfl_xor_sync(0xffffffffu, v2, off);
        v3 += __shfl_xor_sync(0xffffffffu, v3, off);
    }
    const int warp = tid >> 5;
    if ((tid & 31) == 0) {
        red[warp][0] = v0; red[warp][1] = v1;
        red[warp][2] = v2; red[warp][3] = v3;
    }
    __syncthreads();
    if (tid < 4) {
        float s = red[0][tid] + red[1][tid] + red[2][tid] + red[3][tid];
        atomicAdd(&g_acc[tid], s);   // return unused -> RED, no ordering op
    }
}

__global__ __launch_bounds__(32) void finalize_k(float* __restrict__ out) {
    if (threadIdx.x == 0) {
        const float invN = 1.0f / (float)NSAMP;
        float a0 = g_acc[0], a1 = g_acc[1], a2 = g_acc[2], a3 = g_acc[3];
        float reg     = 5.0f * a0 * invN;
        float contain = a1 * invN;
        float noobj   = 0.5f * a2 * invN;
        float cls     = a3 * invN;
        out[0] = reg + contain + noobj + cls;
        out[1] = reg;
        out[2] = contain;
        out[3] = noobj;
        out[4] = cls;
        // reset for the next graph replay; kernel boundary publishes these
        g_acc[0] = 0.0f; g_acc[1] = 0.0f; g_acc[2] = 0.0f; g_acc[3] = 0.0f;
    }
}

extern "C" void kernel_launch(void* const* d_in, const int* in_sizes, int n_in,
                              void* d_out, int out_size)
{
    const float* pred = (const float*)d_in[0];
    const float* tbox = (const float*)d_in[1];
    const float* tcls = (const float*)d_in[2];
    const int*   mask = (const int*)d_in[3];
    float* out = (float*)d_out;

    yolo_k<<<NBLK, CPB>>>(pred, tbox, tcls, mask);
    finalize_k<<<1, 32>>>(out);
}

// round 9
// speedup vs baseline: 1.4121x; 1.0072x over previous
#include <cuda_runtime.h>

// YoloLoss: N=4096, S=14, B=2, NUM_CLS=20.
// Main kernel: single pass — cls loss fused into the staging stream,
// smem only holds the 10 box channels per cell. Fire-and-forget REDs.
// Tiny finalize kernel scales + writes the 5 outputs and resets state.
// NO gpu-scope fences anywhere (measured +15us L1-flush penalty R3/R5/R7).
// inputs: pred_tensor (N,S,S,30) f32, target_boxes (N,S,S,4) f32,
//         target_cls (N,S,S,20) f32, has_object_map (N,S,S) int32
// output: 5 f32 = (total, reg, contain_conf, no_obj, cls)

static constexpr int NSAMP = 4096;
static constexpr int S2    = 14 * 14;
static constexpr int NCELL = NSAMP * S2;   // 802816
static constexpr int CPB   = 128;          // cells (== threads) per block
static constexpr int NBLK  = NCELL / CPB;  // 6272

// accumulators: reg_sum(raw), contain_sum, noobj_sum(raw), cls_sum.
// zero-initialized at load; finalize_k resets them each run (kernel-boundary
// ordering) -> every graph replay starts clean.
__device__ float g_acc[4];

__global__ __launch_bounds__(CPB, 16) void yolo_k(
    const float* __restrict__ pred,
    const float* __restrict__ tbox,
    const float* __restrict__ tcls,
    const int* __restrict__ mask)
{
    // box channels only: stride 11 (odd -> conflict-free per-cell reads)
    __shared__ float sp[CPB * 11];      // 5632 B
    __shared__ float smask[CPB];
    __shared__ float red[CPB / 32][4];

    const int tid = threadIdx.x;
    const long base = (long)blockIdx.x * CPB;

    // mask first: the fused staging loop needs smask[] for cls terms
    smask[tid] = (mask[base + tid] != 0) ? 1.0f : 0.0f;
    __syncthreads();

    // --- fused staging: pred float2 stream; box pairs -> smem,
    //     cls pairs -> immediate (p - t)^2 * m accumulation.
    //     30 even => a pair never splits a cell; pairs never straddle
    //     the ch=10 box/cls boundary (pairs start at even ch).
    const float2* __restrict__ pg2 =
        reinterpret_cast<const float2*>(pred + base * 30);
    const float* __restrict__ cg = tcls + base * 20;
    float cls = 0.0f;
#pragma unroll
    for (int i = 0; i < 15; i++) {
        int idx2 = tid + i * CPB;       // 0..1919
        float2 v = pg2[idx2];
        int e    = idx2 * 2;
        int cell = e / 30;
        int ch   = e - cell * 30;       // even
        if (ch < 10) {
            sp[cell * 11 + ch]     = v.x;
            sp[cell * 11 + ch + 1] = v.y;
        } else {
            const float2 t =
                *reinterpret_cast<const float2*>(cg + cell * 20 + (ch - 10));
            float d0 = v.x - t.x, d1 = v.y - t.y;
            cls += (d0 * d0 + d1 * d1) * smask[cell];
        }
    }
    __syncthreads();

    // --- per-cell box terms ---
    const float4 tb = reinterpret_cast<const float4*>(tbox)[base + tid];
    const float  m  = smask[tid];
    const float* P  = &sp[tid * 11];

    float c0 = P[4], c1 = P[9];
    float noobj = (c0 * c0 + c1 * c1) * (1.0f - m);   // 0.5 at finalize

    const float invS = 1.0f / 14.0f;
    float gx1 = tb.x * invS - 0.5f * tb.z, gx2 = tb.x * invS + 0.5f * tb.z;
    float gy1 = tb.y * invS - 0.5f * tb.w, gy2 = tb.y * invS + 0.5f * tb.w;
    float area_g = (gx2 - gx1) * (gy2 - gy1);

    float iou0, iou1;
#pragma unroll
    for (int b = 0; b < 2; b++) {
        float px = P[5 * b + 0], py = P[5 * b + 1];
        float pw = P[5 * b + 2], ph = P[5 * b + 3];
        float px1 = px * invS - 0.5f * pw, px2 = px * invS + 0.5f * pw;
        float py1 = py * invS - 0.5f * ph, py2 = py * invS + 0.5f * ph;
        float iw = fmaxf(fminf(px2, gx2) - fmaxf(px1, gx1), 0.0f);
        float ih = fmaxf(fminf(py2, gy2) - fmaxf(py1, gy1), 0.0f);
        float inter  = iw * ih;
        float area_p = (px2 - px1) * (py2 - py1);
        float v = inter / (area_p + area_g - inter);
        if (b == 0) iou0 = v; else iou1 = v;
    }
    // jnp.argmax keeps first max on ties -> strict '>' for box 1
    const int best = (iou1 > iou0) ? 1 : 0;
    const float bx = P[5 * best + 0], by = P[5 * best + 1];
    const float bw = P[5 * best + 2], bh = P[5 * best + 3];
    const float bc = P[5 * best + 4];

    float dx = bx - tb.x, dy = by - tb.y;
    float dw = sqrtf(bw) - sqrtf(tb.z);
    float dh = sqrtf(bh) - sqrtf(tb.w);
    float regp = (dx * dx + dy * dy + dw * dw + dh * dh) * m; // L_COORD at finalize
    float dc = bc - 1.0f;
    float contain = dc * dc * m;

    // --- reduction: warp shuffle -> smem -> 4 fire-and-forget REDs ---
    float v0 = regp, v1 = contain, v2 = noobj, v3 = cls;
#pragma unroll
    for (int off = 16; off > 0; off >>= 1) {
        v0 += __shfl_xor_sync(0xffffffffu, v0, off);
        v1 += __shfl_xor_sync(0xffffffffu, v1, off);
        v2 += __shfl_xor_sync(0xffffffffu, v2, off);
        v3 += __shfl_xor_sync(0xffffffffu, v3, off);
    }
    const int warp = tid >> 5;
    if ((tid & 31) == 0) {
        red[warp][0] = v0; red[warp][1] = v1;
        red[warp][2] = v2; red[warp][3] = v3;
    }
    __syncthreads();
    if (tid < 4) {
        float s = red[0][tid] + red[1][tid] + red[2][tid] + red[3][tid];
        atomicAdd(&g_acc[tid], s);   // return unused -> RED, no ordering op
    }
}

__global__ __launch_bounds__(32) void finalize_k(float* __restrict__ out) {
    if (threadIdx.x == 0) {
        const float invN = 1.0f / (float)NSAMP;
        float a0 = g_acc[0], a1 = g_acc[1], a2 = g_acc[2], a3 = g_acc[3];
        float reg     = 5.0f * a0 * invN;
        float contain = a1 * invN;
        float noobj   = 0.5f * a2 * invN;
        float cls     = a3 * invN;
        out[0] = reg + contain + noobj + cls;
        out[1] = reg;
        out[2] = contain;
        out[3] = noobj;
        out[4] = cls;
        // reset for the next graph replay; kernel boundary publishes these
        g_acc[0] = 0.0f; g_acc[1] = 0.0f; g_acc[2] = 0.0f; g_acc[3] = 0.0f;
    }
}

extern "C" void kernel_launch(void* const* d_in, const int* in_sizes, int n_in,
                              void* d_out, int out_size)
{
    const float* pred = (const float*)d_in[0];
    const float* tbox = (const float*)d_in[1];
    const float* tcls = (const float*)d_in[2];
    const int*   mask = (const int*)d_in[3];
    float* out = (float*)d_out;

    yolo_k<<<NBLK, CPB>>>(pred, tbox, tcls, mask);
    finalize_k<<<1, 32>>>(out);
}

// round 10
// speedup vs baseline: 1.4316x; 1.0138x over previous
#include <cuda_runtime.h>

// YoloLoss: N=4096, S=14, B=2, NUM_CLS=20.
// Single worker kernel REDs pre-scaled partials directly into d_out[0..5);
// d_out is zeroed by a graph memset node (no finalize kernel, no g_acc).
// NO gpu-scope fences anywhere (measured +15us L1-flush penalty R3/R5/R7).
// inputs: pred_tensor (N,S,S,30) f32, target_boxes (N,S,S,4) f32,
//         target_cls (N,S,S,20) f32, has_object_map (N,S,S) int32
// output: 5 f32 = (total, reg, contain_conf, no_obj, cls)

static constexpr int NSAMP   = 4096;
static constexpr int S2      = 14 * 14;
static constexpr int NCELL   = NSAMP * S2;    // 802816
static constexpr int THREADS = 128;
static constexpr int CELLS   = 256;           // cells per block (2 per thread)
static constexpr int NBLK    = NCELL / CELLS; // 3136

__global__ __launch_bounds__(THREADS, 12) void yolo_k(
    const float* __restrict__ pred,
    const float* __restrict__ tbox,
    const float* __restrict__ tcls,
    const int* __restrict__ mask,
    float* __restrict__ out)
{
    // box channels only: stride 11 (odd -> conflict-free per-cell reads)
    __shared__ float sp[CELLS * 11];      // 11264 B
    __shared__ float smask[CELLS];
    __shared__ float red[THREADS / 32][4];

    const int tid = threadIdx.x;
    const long base = (long)blockIdx.x * CELLS;

    // mask first: the fused staging loop needs smask[] for cls terms
    smask[tid]           = (mask[base + tid] != 0) ? 1.0f : 0.0f;
    smask[tid + THREADS] = (mask[base + tid + THREADS] != 0) ? 1.0f : 0.0f;
    __syncthreads();

    // --- fused staging: pred float2 stream (30 LDGs/thread, deep MLP);
    //     box pairs -> smem, cls pairs -> immediate (p-t)^2 * m.
    //     30 even => a pair never splits a cell and never straddles ch=10.
    const float2* __restrict__ pg2 =
        reinterpret_cast<const float2*>(pred + base * 30);
    const float* __restrict__ cg = tcls + base * 20;
    float cls = 0.0f;
#pragma unroll
    for (int i = 0; i < 30; i++) {
        int idx2 = tid + i * THREADS;    // 0..3839
        float2 v = pg2[idx2];
        int e    = idx2 * 2;
        int cell = e / 30;
        int ch   = e - cell * 30;        // even
        if (ch < 10) {
            sp[cell * 11 + ch]     = v.x;
            sp[cell * 11 + ch + 1] = v.y;
        } else {
            const float2 t =
                *reinterpret_cast<const float2*>(cg + cell * 20 + (ch - 10));
            float d0 = v.x - t.x, d1 = v.y - t.y;
            cls += (d0 * d0 + d1 * d1) * smask[cell];
        }
    }
    __syncthreads();

    // --- per-cell box terms: 2 independent cells per thread (ILP) ---
    const float4* __restrict__ tb4 = reinterpret_cast<const float4*>(tbox);
    float regp = 0.0f, contain = 0.0f, noobj = 0.0f;
    const float invS = 1.0f / 14.0f;
#pragma unroll
    for (int c = 0; c < 2; c++) {
        const int   lc = tid + c * THREADS;
        const float4 tb = tb4[base + lc];        // x,y,w,h
        const float  m  = smask[lc];
        const float* P  = &sp[lc * 11];

        float c0 = P[4], c1 = P[9];
        noobj += (c0 * c0 + c1 * c1) * (1.0f - m);   // 0.5 applied pre-RED

        float gx1 = tb.x * invS - 0.5f * tb.z, gx2 = tb.x * invS + 0.5f * tb.z;
        float gy1 = tb.y * invS - 0.5f * tb.w, gy2 = tb.y * invS + 0.5f * tb.w;
        float area_g = (gx2 - gx1) * (gy2 - gy1);

        float iou0, iou1;
#pragma unroll
        for (int b = 0; b < 2; b++) {
            float px = P[5 * b + 0], py = P[5 * b + 1];
            float pw = P[5 * b + 2], ph = P[5 * b + 3];
            float px1 = px * invS - 0.5f * pw, px2 = px * invS + 0.5f * pw;
            float py1 = py * invS - 0.5f * ph, py2 = py * invS + 0.5f * ph;
            float iw = fmaxf(fminf(px2, gx2) - fmaxf(px1, gx1), 0.0f);
            float ih = fmaxf(fminf(py2, gy2) - fmaxf(py1, gy1), 0.0f);
            float inter  = iw * ih;
            float area_p = (px2 - px1) * (py2 - py1);
            float v = inter / (area_p + area_g - inter);
            if (b == 0) iou0 = v; else iou1 = v;
        }
        // jnp.argmax keeps first max on ties -> strict '>' for box 1
        const int best = (iou1 > iou0) ? 1 : 0;
        const float bx = P[5 * best + 0], by = P[5 * best + 1];
        const float bw = P[5 * best + 2], bh = P[5 * best + 3];
        const float bc = P[5 * best + 4];

        float dx = bx - tb.x, dy = by - tb.y;
        float dw = sqrtf(bw) - sqrtf(tb.z);
        float dh = sqrtf(bh) - sqrtf(tb.w);
        regp += (dx * dx + dy * dy + dw * dw + dh * dh) * m;
        float dc = bc - 1.0f;
        contain += dc * dc * m;
    }

    // --- reduction: warp shuffle -> smem -> 5 fire-and-forget REDs to out ---
    float v0 = regp, v1 = contain, v2 = noobj, v3 = cls;
#pragma unroll
    for (int off = 16; off > 0; off >>= 1) {
        v0 += __shfl_xor_sync(0xffffffffu, v0, off);
        v1 += __shfl_xor_sync(0xffffffffu, v1, off);
        v2 += __shfl_xor_sync(0xffffffffu, v2, off);
        v3 += __shfl_xor_sync(0xffffffffu, v3, off);
    }
    const int warp = tid >> 5;
    if ((tid & 31) == 0) {
        red[warp][0] = v0; red[warp][1] = v1;
        red[warp][2] = v2; red[warp][3] = v3;
    }
    __syncthreads();
    if (tid < 5) {
        float s0 = red[0][0] + red[1][0] + red[2][0] + red[3][0]; // reg raw
        float s1 = red[0][1] + red[1][1] + red[2][1] + red[3][1]; // contain
        float s2 = red[0][2] + red[1][2] + red[2][2] + red[3][2]; // noobj raw
        float s3 = red[0][3] + red[1][3] + red[2][3] + red[3][3]; // cls
        const float invN = 1.0f / (float)NSAMP;
        float val;
        switch (tid) {
            case 0: val = (5.0f * s0 + s1 + 0.5f * s2 + s3) * invN; break;
            case 1: val = 5.0f * s0 * invN; break;
            case 2: val = s1 * invN; break;
            case 3: val = 0.5f * s2 * invN; break;
            default: val = s3 * invN; break;
        }
        atomicAdd(&out[tid], val);   // return unused -> RED, no ordering op
    }
}

extern "C" void kernel_launch(void* const* d_in, const int* in_sizes, int n_in,
                              void* d_out, int out_size)
{
    const float* pred = (const float*)d_in[0];
    const float* tbox = (const float*)d_in[1];
    const float* tcls = (const float*)d_in[2];
    const int*   mask = (const int*)d_in[3];
    float* out = (float*)d_out;

    // graph memset node: zero the 5 output floats each replay (REDs add onto it)
    cudaMemsetAsync(out, 0, 5 * sizeof(float), 0);
    yolo_k<<<NBLK, THREADS>>>(pred, tbox, tcls, mask, out);
}